// round 15
// baseline (speedup 1.0000x reference)
#include <cuda_runtime.h>

// Problem constants (from reference)
#define KORD 8
#define NUMI 15
#define GBAS (NUMI + KORD)        // 23 basis functions
#define BB 1024
#define NN 34
#define HH 256
#define WW 256
#define IMG_FLOATS (2 * HH * WW)  // 131072 floats per image
#define IMG_F4 (IMG_FLOATS / 4)   // 32768 float4 per image
#define CH_STRIDE (HH * WW)

#define ZPB 4                     // zero-blocks per image
#define GRID (BB * ZPB)           // 4096 blocks (R1's proven zero shape)
#define BLOCK 256
#define SLAB_F4 (IMG_F4 / ZPB)    // 8192 float4 = 128 KB contiguous per block

// Monotonic per-image arrival counters. Each replay adds exactly ZPB per
// image; the block seeing (old % ZPB)==ZPB-1 is that replay's winner and
// performs the scatter. No reset -> re-entrant across graph replays,
// identical work every call. (Pattern validated in round 14.)
__device__ unsigned int g_ctr[BB];

// Order-8 B-spline KAN edge via local de Boor (uniform knots h=4/15: all
// denominators are compile-time constants -> pure FFMA, 9 registers).
// Out-of-range x: reference indicators all zero -> only base*silu survives.
// Tables read directly from global (tiny, L2-resident after first winners).
__device__ __forceinline__ float spline_apply_one(float x, int id,
                                                  const float* __restrict__ coef,
                                                  const float* __restrict__ base) {
    float res = __ldg(base + id) * __fdividef(x, 1.0f + __expf(-x));

    const float invh = 15.0f / 4.0f;
    const float g0   = -2.0f - (float)KORD * (4.0f / 15.0f);  // grid[0]

    float u = (x - g0) * invh;
    float mf = floorf(u);
    int m = (int)mf;
    if (m < 0 || m > 30) return res;
    float t = u - mf;

    float N[KORD + 1];
    N[0] = 1.0f;
#pragma unroll
    for (int j = 1; j <= KORD; j++) {
        const float invj = 1.0f / (float)j;
        float saved = 0.0f;
#pragma unroll
        for (int r = 0; r < j; r++) {
            float temp = N[r] * invj;
            N[r] = saved + ((float)(r + 1) - t) * temp;
            saved = (t + (float)(j - 1 - r)) * temp;
        }
        N[j] = saved;
    }

    const float* crow = coef + id * GBAS;
#pragma unroll
    for (int r = 0; r <= KORD; r++) {
        int jdx = m - KORD + r;
        if (jdx >= 0 && jdx < GBAS)
            res += __ldg(crow + jdx) * N[r];
    }
    return res;
}

// Single kernel, 4096 blocks x 256 threads (8/SM). Every block:
//   1. optimistically stages its image's point coords (overlaps store stream)
//   2. zeroes ONE contiguous 128 KB slab (pure linear float4 stream — the
//      exact shape that measured ~7.0 TB/s standalone)
//   3. arrives on its image's counter; 3 of 4 blocks exit immediately.
// The 4th arriver (zeros of all 4 slabs visible via fence/atomic/fence)
// scatters the image's 34 points: collision scan in smem, two stacked
// spline evals, two 4-byte stores.
__global__ void __launch_bounds__(BLOCK, 8)
vec2im_kernel(const float* __restrict__ xv,
              const float* __restrict__ dcoef,
              const float* __restrict__ dbase,
              const float* __restrict__ ccoef,
              const float* __restrict__ cbase,
              float* __restrict__ out) {
    __shared__ int s_cx[NN];
    __shared__ int s_cy[NN];
    __shared__ int s_last;

    const int tid = threadIdx.x;
    const int bid = blockIdx.x;
    const int img = bid >> 2;          // image this block contributes to

    // ---- Optimistic point stage (long-latency loads issued first) ----
    float power = 0.f; int cx = 0, cy = 0, dev = 0, cat = 0;
    if (tid < NN) {
        const float* v = xv + ((size_t)img * NN + tid) * 5;
        power = v[0];
        cx = (int)rintf(v[1]);
        cy = (int)rintf(v[2]);
        dev = (int)v[3];
        cat = (int)v[4];
        s_cx[tid] = cx;
        s_cy[tid] = cy;
    }

    // ---- Zero one contiguous 128 KB slab (linear across blockIdx) ----
    {
        float4* dst = (float4*)out + (size_t)bid * SLAB_F4;
        const float4 z = make_float4(0.f, 0.f, 0.f, 0.f);
#pragma unroll 8
        for (int i = tid; i < SLAB_F4; i += BLOCK) dst[i] = z;
    }

    // ---- Arrive; winner (last of 4) scatters ----
    __syncthreads();                   // slab stores issued, coords staged
    if (tid == 0) {
        __threadfence();               // release my zeros
        unsigned int old = atomicAdd(&g_ctr[img], 1u);
        s_last = ((old & (ZPB - 1)) == (ZPB - 1)) ? 1 : 0;
    }
    __syncthreads();
    if (!s_last) return;               // 3 of 4 blocks: pure zero role
    __threadfence();                   // acquire all 4 slabs' zeros

    if (tid >= NN) return;

    // Last-write-wins in index order: dead if any LATER point collides.
    bool dead = false;
#pragma unroll 4
    for (int m = tid + 1; m < NN; m++)
        dead |= (s_cx[m] == cx) & (s_cy[m] == cy);
    if (dead) return;

    const size_t base_off = (size_t)img * IMG_FLOATS;
    const size_t pix = (size_t)cy * WW + cx;
    out[base_off + CH_STRIDE + pix] = power;   // ch1 early (no spline)

    float p = spline_apply_one(power, dev, dcoef, dbase);
    p       = spline_apply_one(p,     cat, ccoef, cbase);
    out[base_off + pix] = p;                   // ch0
}

extern "C" void kernel_launch(void* const* d_in, const int* in_sizes, int n_in,
                              void* d_out, int out_size) {
    const float* xv    = (const float*)d_in[0]; // (1024,34,5)
    const float* dcoef = (const float*)d_in[1]; // (34,23)
    const float* dbase = (const float*)d_in[2]; // (34,)
    const float* ccoef = (const float*)d_in[3]; // (5,23)
    const float* cbase = (const float*)d_in[4]; // (5,)
    float* out = (float*)d_out;                 // (1024,2,256,256)

    vec2im_kernel<<<GRID, BLOCK>>>(xv, dcoef, dbase, ccoef, cbase, out);
}

// round 16
// speedup vs baseline: 1.0873x; 1.0873x over previous
#include <cuda_runtime.h>

// Problem constants (from reference)
#define KORD 8
#define NUMI 15
#define GBAS (NUMI + KORD)        // 23 basis functions
#define BB 1024
#define NN 34
#define HH 256
#define WW 256
#define IMG_FLOATS (2 * HH * WW)  // 131072 floats per image
#define CH_STRIDE (HH * WW)
#define IMG_PER_BLK 4
#define NBLK (BB / IMG_PER_BLK)   // 256 blocks

// Order-8 B-spline KAN edge via local de Boor: only the K+1=9 basis functions
// covering x are nonzero. Uniform knots (h = 4/15) make every denominator in
// the triangular recurrence a compile-time constant -> pure FFMA, 9 registers.
// Out-of-range x: all reference indicators are zero -> only base*silu survives.
// Tables read via __ldg (4 KB total, L1/L2-resident across the grid).
__device__ __forceinline__ float spline_apply_one(float x, int id,
                                                  const float* __restrict__ coef,
                                                  const float* __restrict__ base) {
    float res = __ldg(base + id) * __fdividef(x, 1.0f + __expf(-x));

    const float invh = 15.0f / 4.0f;
    const float g0   = -2.0f - (float)KORD * (4.0f / 15.0f);  // grid[0]

    float u = (x - g0) * invh;                        // position in knot units
    float mf = floorf(u);
    int m = (int)mf;
    if (m < 0 || m > 30) return res;                  // outside knot range
    float t = u - mf;                                 // local coord in [0,1)

    // de Boor: N[r] = B_{m-8+r}(x) after the last iteration
    float N[KORD + 1];
    N[0] = 1.0f;
#pragma unroll
    for (int j = 1; j <= KORD; j++) {
        const float invj = 1.0f / (float)j;           // compile-time constant
        float saved = 0.0f;
#pragma unroll
        for (int r = 0; r < j; r++) {
            float temp = N[r] * invj;
            N[r] = saved + ((float)(r + 1) - t) * temp;
            saved = (t + (float)(j - 1 - r)) * temp;
        }
        N[j] = saved;
    }

    const float* crow = coef + id * GBAS;
#pragma unroll
    for (int r = 0; r <= KORD; r++) {
        int jdx = m - KORD + r;
        if (jdx >= 0 && jdx < GBAS)
            res += __ldg(crow + jdx) * N[r];
    }
    return res;
}

// 4 images per 256-thread block (256 blocks). Each 64-thread group owns one
// image; thread n<34 loads its point's 5 floats directly. Rounded coords go
// to smem; ONE sync guards only the coord exchange (no table staging —
// tables are __ldg'd on demand, cached). Channel-1 store (raw power, no
// spline) issues right after the collision check so its write latency
// drains under the two spline evaluations.
__global__ void __launch_bounds__(256)
scatter_kernel(const float* __restrict__ xv,
               const float* __restrict__ dcoef,
               const float* __restrict__ dbase,
               const float* __restrict__ ccoef,
               const float* __restrict__ cbase,
               float* __restrict__ out) {
    __shared__ int s_cx[IMG_PER_BLK][NN];
    __shared__ int s_cy[IMG_PER_BLK][NN];

    const int tid = threadIdx.x;
    const int sub = tid >> 6;          // image within block (0..3)
    const int n = tid & 63;            // point within image
    const int b = blockIdx.x * IMG_PER_BLK + sub;

    // Per-point direct loads (longest-latency chain head, issued first)
    float power = 0.f; int cx = 0, cy = 0, dev = 0, cat = 0;
    if (n < NN) {
        const float* v = xv + ((size_t)b * NN + n) * 5;
        power = v[0];
        cx = (int)rintf(v[1]);
        cy = (int)rintf(v[2]);
        dev = (int)v[3];
        cat = (int)v[4];
        s_cx[sub][n] = cx;
        s_cy[sub][n] = cy;
    }

    __syncthreads();                   // coords visible

    if (n >= NN) return;

    // Last-write-wins in index order: dead if any LATER point collides.
    bool dead = false;
#pragma unroll 4
    for (int m = n + 1; m < NN; m++)
        dead |= (s_cx[sub][m] == cx) & (s_cy[sub][m] == cy);
    if (dead) return;

    const size_t base_off = (size_t)b * IMG_FLOATS;
    const size_t pix = (size_t)cy * WW + cx;

    // Channel 1 store first — needs no spline, drains under the compute.
    out[base_off + CH_STRIDE + pix] = power;

    float p = spline_apply_one(power, dev, dcoef, dbase);
    p       = spline_apply_one(p,     cat, ccoef, cbase);

    out[base_off + pix] = p;           // channel 0
}

extern "C" void kernel_launch(void* const* d_in, const int* in_sizes, int n_in,
                              void* d_out, int out_size) {
    const float* xv    = (const float*)d_in[0]; // (1024,34,5)
    const float* dcoef = (const float*)d_in[1]; // (34,23)
    const float* dbase = (const float*)d_in[2]; // (34,)
    const float* ccoef = (const float*)d_in[3]; // (5,23)
    const float* cbase = (const float*)d_in[4]; // (5,)
    float* out = (float*)d_out;                 // (1024,2,256,256)

    // Phase 1: single driver bulk zero-fill. Measured 7.2 TB/s — faster than
    // any SM store loop (pure-write stream, no read/write turnaround), and a
    // single node (split memsets regress). This is the roofline term.
    cudaMemsetAsync(out, 0, (size_t)out_size * sizeof(float), 0);

    // Phase 2: minimal sparse scatter, 4 images per block.
    scatter_kernel<<<NBLK, 256>>>(xv, dcoef, dbase, ccoef, cbase, out);
}

// round 17
// speedup vs baseline: 1.0922x; 1.0045x over previous
#include <cuda_runtime.h>

// Problem constants (from reference)
#define KORD 8
#define NUMI 15
#define GBAS (NUMI + KORD)        // 23 basis functions
#define BB 1024
#define NN 34
#define HH 256
#define WW 256
#define IMG_FLOATS (2 * HH * WW)  // 131072 floats per image
#define CH_STRIDE (HH * WW)
#define IMG_PER_BLK 4
#define NBLK (BB / IMG_PER_BLK)   // 256 blocks

// Order-8 B-spline KAN edge via local de Boor: only the K+1=9 basis functions
// covering x are nonzero. Uniform knots (h = 4/15) make every denominator in
// the triangular recurrence a compile-time constant -> pure FFMA, 9 registers.
// Out-of-range x: all reference indicators are zero -> only base*silu survives.
// coef/base point to SHARED memory (bulk-staged tables: independent prefetch
// measured faster than on-demand __ldg -- R16 regression test).
__device__ __forceinline__ float spline_apply_one(float x, int id,
                                                  const float* coef,
                                                  const float* base) {
    float res = base[id] * __fdividef(x, 1.0f + __expf(-x));  // base * silu

    const float invh = 15.0f / 4.0f;
    const float g0   = -2.0f - (float)KORD * (4.0f / 15.0f);  // grid[0]

    float u = (x - g0) * invh;                        // position in knot units
    float mf = floorf(u);
    int m = (int)mf;
    if (m < 0 || m > 30) return res;                  // outside knot range
    float t = u - mf;                                 // local coord in [0,1)

    // de Boor: N[r] = B_{m-8+r}(x) after the last iteration
    float N[KORD + 1];
    N[0] = 1.0f;
#pragma unroll
    for (int j = 1; j <= KORD; j++) {
        const float invj = 1.0f / (float)j;           // compile-time constant
        float saved = 0.0f;
#pragma unroll
        for (int r = 0; r < j; r++) {
            float temp = N[r] * invj;
            N[r] = saved + ((float)(r + 1) - t) * temp;
            saved = (t + (float)(j - 1 - r)) * temp;
        }
        N[j] = saved;
    }

    const float* crow = coef + id * GBAS;
#pragma unroll
    for (int r = 0; r <= KORD; r++) {
        int jdx = m - KORD + r;
        if (jdx >= 0 && jdx < GBAS)
            res += crow[jdx] * N[r];
    }
    return res;
}

// 4 images per 256-thread block (256 blocks). Each 64-thread group owns one
// image; thread n<34 loads its point's 5 floats directly (each image row is
// 6 cache lines, shared by the whole group). Rounded coords go to smem; the
// spline tables (3.6 KB) are bulk-staged with INDEPENDENT loads that overlap
// the xv latency; ONE sync covers both. Channel-1 store (raw power, no
// spline needed) issues immediately after the collision check so its write
// latency drains under the two spline evaluations.
__global__ void __launch_bounds__(256)
scatter_kernel(const float* __restrict__ xv,
               const float* __restrict__ dcoef,
               const float* __restrict__ dbase,
               const float* __restrict__ ccoef,
               const float* __restrict__ cbase,
               float* __restrict__ out) {
    __shared__ float s_dc[34 * GBAS];              // 782 floats
    __shared__ float s_db[34];
    __shared__ float s_cc[5 * GBAS];               // 115 floats
    __shared__ float s_cb[5];
    __shared__ int   s_cx[IMG_PER_BLK][NN];
    __shared__ int   s_cy[IMG_PER_BLK][NN];

    const int tid = threadIdx.x;
    const int sub = tid >> 6;          // image within block (0..3)
    const int n = tid & 63;            // point within image
    const int b = blockIdx.x * IMG_PER_BLK + sub;

    // Per-point direct loads (issued first: longest-latency chain head)
    float power = 0.f; int cx = 0, cy = 0, dev = 0, cat = 0;
    if (n < NN) {
        const float* v = xv + ((size_t)b * NN + n) * 5;
        power = v[0];
        cx = (int)rintf(v[1]);
        cy = (int)rintf(v[2]);
        dev = (int)v[3];
        cat = (int)v[4];
        s_cx[sub][n] = cx;
        s_cy[sub][n] = cy;
    }

    // Table staging (independent loads, overlap the xv latency)
#pragma unroll
    for (int i = tid; i < 34 * GBAS; i += 256) s_dc[i] = dcoef[i];
    if (tid < 34) s_db[tid] = dbase[tid];
    else if (tid >= 64 && tid < 64 + 5 * GBAS) s_cc[tid - 64] = ccoef[tid - 64];
    else if (tid >= 192 && tid < 197) s_cb[tid - 192] = cbase[tid - 192];

    __syncthreads();                   // coords + tables visible

    if (n >= NN) return;

    // Last-write-wins in index order: dead if any LATER point collides.
    bool dead = false;
#pragma unroll 4
    for (int m = n + 1; m < NN; m++)
        dead |= (s_cx[sub][m] == cx) & (s_cy[sub][m] == cy);
    if (dead) return;

    const size_t base_off = (size_t)b * IMG_FLOATS;
    const size_t pix = (size_t)cy * WW + cx;

    // Channel 1 store first — needs no spline, drains under the compute.
    out[base_off + CH_STRIDE + pix] = power;

    float p = spline_apply_one(power, dev, s_dc, s_db);
    p       = spline_apply_one(p,     cat, s_cc, s_cb);

    out[base_off + pix] = p;           // channel 0
}

extern "C" void kernel_launch(void* const* d_in, const int* in_sizes, int n_in,
                              void* d_out, int out_size) {
    const float* xv    = (const float*)d_in[0]; // (1024,34,5)
    const float* dcoef = (const float*)d_in[1]; // (34,23)
    const float* dbase = (const float*)d_in[2]; // (34,)
    const float* ccoef = (const float*)d_in[3]; // (5,23)
    const float* cbase = (const float*)d_in[4]; // (5,)
    float* out = (float*)d_out;                 // (1024,2,256,256)

    // Phase 1: single driver bulk zero-fill. Measured 7.2 TB/s — faster than
    // every SM store loop tried (pure-write stream, no read/write
    // turnaround) and must stay one node (split memsets regress).
    cudaMemsetAsync(out, 0, (size_t)out_size * sizeof(float), 0);

    // Phase 2: minimal sparse scatter, 4 images per block (6.8 us measured).
    scatter_kernel<<<NBLK, 256>>>(xv, dcoef, dbase, ccoef, cbase, out);
}